// round 13
// baseline (speedup 1.0000x reference)
#include <cuda_runtime.h>
#include <cuda_fp16.h>
#include <cstdint>

typedef unsigned long long ull;

#define BS    8
#define NPTS  1024
#define JJ    3
#define KIN   96
#define FOUT  64
#define ROWS  (BS*NPTS)      // 8192
#define KSPL  2
#define MSEG  (NPTS/KSPL)    // 512
#define MC    32             // m per chunk
#define NCH   (MSEG/MC)      // 16
#define MT    64             // n rows per block
#define NT1   (NPTS/MT)      // 16
#define ATB   8192           // A tile bytes (64 rows x 128B)
#define BTB   4096           // B tile bytes (32 rows x 128B)
#define K2ROWS 32
#define NBLK2 (ROWS/K2ROWS)  // 256
#define PYT2  36

__device__ __align__(16) float g_yp[KSPL*ROWS*KIN];   // 6.3 MB partials
__device__ float g_psum[NBLK2*FOUT];
__device__ float g_psq [NBLK2*FOUT];
__device__ float g_coef[2*FOUT];
__device__ int   g_ctr = 0;

// ---------------- helpers ----------------
#define SW128(o) ((o) ^ (((o) >> 3) & 0x70))

__device__ __forceinline__ uint32_t smem_u32(const void* p) {
    uint32_t a;
    asm("{ .reg .u64 t; cvta.to.shared.u64 t, %1; cvt.u32.u64 %0, t; }" : "=r"(a) : "l"(p));
    return a;
}
// fp16 hi/lo split of a float pair -> packed h (f16x2) and residual l (f16x2)
__device__ __forceinline__ void split2h(float a0, float a1, uint32_t& h, uint32_t& l) {
    __half2 h2 = __float22half2_rn(make_float2(a0, a1));
    float r0 = a0 - __low2float(h2);
    float r1 = a1 - __high2float(h2);
    __half2 l2 = __float22half2_rn(make_float2(r0, r1));
    h = *reinterpret_cast<uint32_t*>(&h2);
    l = *reinterpret_cast<uint32_t*>(&l2);
}
__device__ __forceinline__ void sts32(uint32_t a, uint32_t v) {
    asm volatile("st.shared.b32 [%0], %1;" :: "r"(a), "r"(v) : "memory");
}
__device__ __forceinline__ void sts128(uint32_t a, uint32_t v0, uint32_t v1,
                                       uint32_t v2, uint32_t v3) {
    asm volatile("st.shared.v4.b32 [%0], {%1,%2,%3,%4};"
                 :: "r"(a), "r"(v0), "r"(v1), "r"(v2), "r"(v3) : "memory");
}
__device__ __forceinline__ void ldmx4(uint32_t* r, uint32_t a) {
    asm volatile("ldmatrix.sync.aligned.m8n8.x4.shared.b16 {%0,%1,%2,%3}, [%4];"
                 : "=r"(r[0]), "=r"(r[1]), "=r"(r[2]), "=r"(r[3]) : "r"(a));
}
__device__ __forceinline__ void mma16816(float* d, const uint32_t* A, const uint32_t* B) {
    asm volatile(
        "mma.sync.aligned.m16n8k16.row.col.f32.f16.f16.f32 "
        "{%0,%1,%2,%3}, {%4,%5,%6,%7}, {%8,%9}, {%0,%1,%2,%3};"
        : "+f"(d[0]), "+f"(d[1]), "+f"(d[2]), "+f"(d[3])
        : "r"(A[0]), "r"(A[1]), "r"(A[2]), "r"(A[3]), "r"(B[0]), "r"(B[1]));
}
__device__ __forceinline__ ull fma2(ull a, ull b, ull c) {
    ull d;
    asm("fma.rn.f32x2 %0, %1, %2, %3;" : "=l"(d) : "l"(a), "l"(b), "l"(c));
    return d;
}
__device__ __forceinline__ ull dup2(float x) {
    unsigned b = __float_as_uint(x);
    return (((ull)b) << 32) | (ull)b;
}

// ---------------- K1: fp16 A-split 2-pass GMul on mma.sync ----------------
__global__ __launch_bounds__(128) void k1_gmul(const float* __restrict__ WW,
                                               const float* __restrict__ X) {
    __shared__ float4 smv[(3*ATB + BTB) / 16];
    const uint32_t sb = smem_u32(smv);
    const uint32_t Bb = sb + 3*ATB;

    const int t = threadIdx.x, warp = t >> 5, lane = t & 31;
    const int b  = blockIdx.y;
    const int n0 = blockIdx.x * MT;
    const int bz = blockIdx.z;

    const float* wwC = WW + ((size_t)(b * NPTS + n0) * NPTS + (size_t)bz * MSEG) * 3;
    const float* xC  = X + (size_t)b * NPTS * 32 + (size_t)bz * MSEG * 32;

    const int ln = t >> 1, mh = (t & 1) * 16;
    const float* wrow = wwC + (size_t)ln * (NPTS * 3) + mh * 3;
    const int mp = t >> 3, xf0 = (t & 7) * 4;
    const float* xrow = xC + 2 * mp * 32 + xf0;

    const int rw = warp * 16;
    const uint32_t aoffL = (uint32_t)(rw + (lane & 15)) * 128 + (lane >> 4) * 16;
    const uint32_t boffL = (uint32_t)(8 * (lane >> 4) + (lane & 7)) * 128 + ((lane >> 3) & 1) * 16;

    float acc[48];
#pragma unroll
    for (int i = 0; i < 48; i++) acc[i] = 0.f;

    float wf[48];
    float4 xr0, xr1;
#pragma unroll
    for (int i = 0; i < 12; i++)
        *(float4*)(wf + 4*i) = *(const float4*)(wrow + 4*i);
    xr0 = *(const float4*)(xrow);
    xr1 = *(const float4*)(xrow + 32);

    for (int c = 0; c < NCH; ++c) {
        // ---- stage A tiles (fp16 hi|lo, SW128) ----
#pragma unroll
        for (int j = 0; j < 3; j++) {
            uint32_t hw[8], lw[8];
#pragma unroll
            for (int p = 0; p < 8; p++)
                split2h(wf[(2*p) * 3 + j], wf[(2*p+1) * 3 + j], hw[p], lw[p]);
            const uint32_t tb = sb + j * ATB;
            const uint32_t rb = (uint32_t)ln * 128 + mh * 2;
            sts128(tb + SW128(rb),      hw[0], hw[1], hw[2], hw[3]);
            sts128(tb + SW128(rb + 16), hw[4], hw[5], hw[6], hw[7]);
            sts128(tb + SW128(rb + 64), lw[0], lw[1], lw[2], lw[3]);
            sts128(tb + SW128(rb + 80), lw[4], lw[5], lw[6], lw[7]);
        }
        // ---- stage B tile (x transposed, single fp16) ----
        {
            float xa[4] = { xr0.x, xr0.y, xr0.z, xr0.w };
            float xb[4] = { xr1.x, xr1.y, xr1.z, xr1.w };
#pragma unroll
            for (int ff = 0; ff < 4; ff++) {
                __half2 h2 = __float22half2_rn(make_float2(xa[ff], xb[ff]));
                uint32_t fr = (uint32_t)(xf0 + ff) * 128 + 4 * mp;
                sts32(Bb + SW128(fr), *reinterpret_cast<uint32_t*>(&h2));
            }
        }
        __syncthreads();

        if (c + 1 < NCH) {
            const float* wp = wrow + (c + 1) * (MC * 3);
#pragma unroll
            for (int i = 0; i < 12; i++)
                *(float4*)(wf + 4*i) = *(const float4*)(wp + 4*i);
            const float* xp = xrow + (c + 1) * (MC * 32);
            xr0 = *(const float4*)(xp);
            xr1 = *(const float4*)(xp + 32);
        }

        // ---- mma: 2 passes (AhB, AlB) ----
#pragma unroll
        for (int ks = 0; ks < 2; ks++) {
            uint32_t Bh[8];
            ldmx4(Bh,     Bb + SW128(boffL + ks*32));
            ldmx4(Bh + 4, Bb + SW128(boffL + 2048 + ks*32));
#pragma unroll
            for (int j = 0; j < 3; j++) {
                uint32_t Ah[4], Al[4];
                const uint32_t ab = sb + j * ATB;
                ldmx4(Ah, ab + SW128(aoffL + ks*32));
                ldmx4(Al, ab + SW128(aoffL + 64 + ks*32));
#pragma unroll
                for (int fb = 0; fb < 4; fb++) {
                    float* d = acc + j*16 + fb*4;
                    mma16816(d, Ah, Bh + 2*fb);
                    mma16816(d, Al, Bh + 2*fb);
                }
            }
        }
        __syncthreads();
    }

    const int g = lane >> 2, tq = lane & 3;
    const size_t row = (size_t)bz * ROWS + (size_t)b * NPTS + n0 + rw + g;
    float* y0 = g_yp + row * KIN;
    float* y1 = y0 + 8 * KIN;
#pragma unroll
    for (int j = 0; j < 3; j++)
#pragma unroll
        for (int fb = 0; fb < 4; fb++) {
            const float* d = acc + j*16 + fb*4;
            const int cb = j*32 + fb*8 + 2*tq;
            float2 lo = { d[0], d[1] };
            float2 hi = { d[2], d[3] };
            *(float2*)(y0 + cb) = lo;
            *(float2*)(y1 + cb) = hi;
        }
}

// ---------------- K2: partial-sum + MLP + BN partials + last-block stats ----------------
__global__ __launch_bounds__(256) void k2_mlp(const float* __restrict__ W1,
                                              const float* __restrict__ W2,
                                              const float* __restrict__ b1,
                                              const float* __restrict__ b2,
                                              const float* __restrict__ gamma,
                                              const float* __restrict__ beta,
                                              float* __restrict__ Z) {
    __shared__ __align__(16) float yT[KIN * PYT2];
    __shared__ __align__(16) float wTs[KIN * FOUT];
    __shared__ float ps[4*FOUT], pq[4*FOUT];
    __shared__ int last_s;

    const int t = threadIdx.x;
    const int row0 = blockIdx.x * K2ROWS;

#pragma unroll
    for (int i = 0; i < 3; i++) {
        int flat = i * 256 + t;
        int r = flat / 24, k4 = flat % 24;
        size_t base = ((size_t)(row0 + r)) * KIN + k4 * 4;
        float4 v0 = *(const float4*)&g_yp[base];
        float4 v1 = *(const float4*)&g_yp[base + (size_t)ROWS*KIN];
        float4 v;
        v.x = v0.x + v1.x; v.y = v0.y + v1.y;
        v.z = v0.z + v1.z; v.w = v0.w + v1.w;
        int sbi = (k4 * 4) * PYT2 + r;
        yT[sbi]            = v.x;
        yT[sbi +     PYT2] = v.y;
        yT[sbi + 2 * PYT2] = v.z;
        yT[sbi + 3 * PYT2] = v.w;
    }
#pragma unroll
    for (int i = 0; i < 3; i++) {
        int idx4 = i * 256 + t;
        int c = idx4 / 24, k4 = idx4 % 24;
        float4 a = *(const float4*)&W1[(size_t)c * KIN + k4 * 4];
        float4 d = *(const float4*)&W2[(size_t)c * KIN + k4 * 4];
        wTs[(k4*4 + 0) * FOUT + c] = a.x;
        wTs[(k4*4 + 1) * FOUT + c] = a.y;
        wTs[(k4*4 + 2) * FOUT + c] = a.z;
        wTs[(k4*4 + 3) * FOUT + c] = a.w;
        wTs[(k4*4 + 0) * FOUT + 32 + c] = d.x;
        wTs[(k4*4 + 1) * FOUT + 32 + c] = d.y;
        wTs[(k4*4 + 2) * FOUT + 32 + c] = d.z;
        wTs[(k4*4 + 3) * FOUT + 32 + c] = d.w;
    }
    __syncthreads();

    const int col = t & 63, rg = t >> 6;
    const int rbase = rg * 8;
    ull acc2[4];
#pragma unroll
    for (int q = 0; q < 4; q++) acc2[q] = 0ULL;

#pragma unroll 4
    for (int k = 0; k < KIN; k++) {
        ull wd = dup2(wTs[k * FOUT + col]);
        const float* yp = yT + k * PYT2 + rbase;
        ulonglong2 y0 = *(const ulonglong2*)(yp);
        ulonglong2 y1 = *(const ulonglong2*)(yp + 4);
        acc2[0] = fma2(y0.x, wd, acc2[0]);
        acc2[1] = fma2(y0.y, wd, acc2[1]);
        acc2[2] = fma2(y1.x, wd, acc2[2]);
        acc2[3] = fma2(y1.y, wd, acc2[3]);
    }

    const float bias = (col < 32) ? __ldg(&b1[col]) : __ldg(&b2[col - 32]);
    float s = 0.f, sq = 0.f;
#pragma unroll
    for (int q = 0; q < 4; q++) {
        union { ull u; float f[2]; } cv; cv.u = acc2[q];
#pragma unroll
        for (int h = 0; h < 2; h++) {
            float z = cv.f[h] + bias;
            if (col < 32) z = fmaxf(z, 0.f);
            Z[((size_t)row0 + rbase + 2*q + h) * FOUT + col] = z;
            s += z; sq += z * z;
        }
    }
    ps[rg * FOUT + col] = s; pq[rg * FOUT + col] = sq;
    __syncthreads();
    if (rg == 0) {
        float S = (ps[col] + ps[FOUT + col]) + (ps[2*FOUT + col] + ps[3*FOUT + col]);
        float Q = (pq[col] + pq[FOUT + col]) + (pq[2*FOUT + col] + pq[3*FOUT + col]);
        g_psum[blockIdx.x * FOUT + col] = S;
        g_psq [blockIdx.x * FOUT + col] = Q;
    }

    __threadfence();
    if (t == 0) last_s = (atomicAdd(&g_ctr, 1) == NBLK2 - 1);
    __syncthreads();
    if (last_s) {
        const int seg = t >> 6;
        float S = 0.f, Q = 0.f;
#pragma unroll 8
        for (int i = 0; i < NBLK2/4; i++) {
            int idx = (seg * (NBLK2/4) + i) * FOUT + col;
            S += g_psum[idx];
            Q += g_psq [idx];
        }
        ps[seg * FOUT + col] = S; pq[seg * FOUT + col] = Q;
        __syncthreads();
        if (t < FOUT) {
            float Sf = (ps[t] + ps[FOUT + t]) + (ps[2*FOUT + t] + ps[3*FOUT + t]);
            float Qf = (pq[t] + pq[FOUT + t]) + (pq[2*FOUT + t] + pq[3*FOUT + t]);
            float mean = Sf * (1.0f / ROWS);
            float var  = Qf * (1.0f / ROWS) - mean * mean;
            float sc   = __ldg(&gamma[t]) * rsqrtf(var + 1e-5f);
            g_coef[t]        = sc;
            g_coef[FOUT + t] = __ldg(&beta[t]) - mean * sc;
        }
        if (t == 0) g_ctr = 0;
    }
}

// ---------------- K4: in-place normalize ----------------
__global__ __launch_bounds__(256) void k4_norm(float* __restrict__ Z) {
    int i0 = blockIdx.x * 512 + threadIdx.x;
    float4* Z4 = (float4*)Z;
    float4 v0 = Z4[i0];
    float4 v1 = Z4[i0 + 256];
    int c = (i0 & 15) * 4;
    float s0 = g_coef[c],   s1 = g_coef[c+1], s2 = g_coef[c+2], s3 = g_coef[c+3];
    float h0 = g_coef[FOUT+c], h1 = g_coef[FOUT+c+1], h2 = g_coef[FOUT+c+2], h3 = g_coef[FOUT+c+3];
    v0.x = v0.x*s0 + h0; v0.y = v0.y*s1 + h1; v0.z = v0.z*s2 + h2; v0.w = v0.w*s3 + h3;
    v1.x = v1.x*s0 + h0; v1.y = v1.y*s1 + h1; v1.z = v1.z*s2 + h2; v1.w = v1.w*s3 + h3;
    Z4[i0] = v0;
    Z4[i0 + 256] = v1;
}

extern "C" void kernel_launch(void* const* d_in, const int* in_sizes, int n_in,
                              void* d_out, int out_size) {
    const float* WW    = (const float*)d_in[0];
    const float* X     = (const float*)d_in[1];
    const float* W1    = (const float*)d_in[2];
    const float* b1    = (const float*)d_in[3];
    const float* W2    = (const float*)d_in[4];
    const float* b2    = (const float*)d_in[5];
    const float* gamma = (const float*)d_in[6];
    const float* beta  = (const float*)d_in[7];
    float* Z = (float*)d_out;

    dim3 g1(NT1, BS, KSPL);
    k1_gmul<<<g1, 128>>>(WW, X);
    k2_mlp<<<NBLK2, 256>>>(W1, W2, b1, b2, gamma, beta, Z);
    k4_norm<<<(ROWS * FOUT / 4) / 512, 256>>>(Z);
}

// round 15
// speedup vs baseline: 1.0056x; 1.0056x over previous
#include <cuda_runtime.h>
#include <cuda_fp16.h>
#include <cstdint>

typedef unsigned long long ull;

#define BS    8
#define NPTS  1024
#define JJ    3
#define KIN   96
#define FOUT  64
#define ROWS  (BS*NPTS)      // 8192
#define KSPL  2
#define MSEG  (NPTS/KSPL)    // 512
#define MC    32             // m per chunk
#define NCH   (MSEG/MC)      // 16
#define MT    64             // n rows per block
#define NT1   (NPTS/MT)      // 16
#define ATB   8192           // A tile bytes (64 rows x 128B)
#define BTB   4096           // B tile bytes (32 rows x 128B)
#define K2ROWS 32
#define NBLK2 (ROWS/K2ROWS)  // 256
#define PYT2  36

__device__ __align__(16) float g_yp[KSPL*ROWS*KIN];   // 6.3 MB partials
__device__ float g_psum[NBLK2*FOUT];
__device__ float g_psq [NBLK2*FOUT];
__device__ float g_coef[2*FOUT];
__device__ int   g_ctr = 0;

// ---------------- helpers ----------------
#define SW128(o) ((o) ^ (((o) >> 3) & 0x70))

__device__ __forceinline__ uint32_t smem_u32(const void* p) {
    uint32_t a;
    asm("{ .reg .u64 t; cvta.to.shared.u64 t, %1; cvt.u32.u64 %0, t; }" : "=r"(a) : "l"(p));
    return a;
}
// fp16 hi/lo split of a float pair -> packed h (f16x2) and residual l (f16x2)
__device__ __forceinline__ void split2h(float a0, float a1, uint32_t& h, uint32_t& l) {
    __half2 h2 = __float22half2_rn(make_float2(a0, a1));
    float r0 = a0 - __low2float(h2);
    float r1 = a1 - __high2float(h2);
    __half2 l2 = __float22half2_rn(make_float2(r0, r1));
    h = *reinterpret_cast<uint32_t*>(&h2);
    l = *reinterpret_cast<uint32_t*>(&l2);
}
__device__ __forceinline__ void sts32(uint32_t a, uint32_t v) {
    asm volatile("st.shared.b32 [%0], %1;" :: "r"(a), "r"(v) : "memory");
}
__device__ __forceinline__ void sts128(uint32_t a, uint32_t v0, uint32_t v1,
                                       uint32_t v2, uint32_t v3) {
    asm volatile("st.shared.v4.b32 [%0], {%1,%2,%3,%4};"
                 :: "r"(a), "r"(v0), "r"(v1), "r"(v2), "r"(v3) : "memory");
}
__device__ __forceinline__ void ldmx4(uint32_t* r, uint32_t a) {
    asm volatile("ldmatrix.sync.aligned.m8n8.x4.shared.b16 {%0,%1,%2,%3}, [%4];"
                 : "=r"(r[0]), "=r"(r[1]), "=r"(r[2]), "=r"(r[3]) : "r"(a));
}
__device__ __forceinline__ void mma16816(float* d, const uint32_t* A, const uint32_t* B) {
    asm volatile(
        "mma.sync.aligned.m16n8k16.row.col.f32.f16.f16.f32 "
        "{%0,%1,%2,%3}, {%4,%5,%6,%7}, {%8,%9}, {%0,%1,%2,%3};"
        : "+f"(d[0]), "+f"(d[1]), "+f"(d[2]), "+f"(d[3])
        : "r"(A[0]), "r"(A[1]), "r"(A[2]), "r"(A[3]), "r"(B[0]), "r"(B[1]));
}
__device__ __forceinline__ ull fma2(ull a, ull b, ull c) {
    ull d;
    asm("fma.rn.f32x2 %0, %1, %2, %3;" : "=l"(d) : "l"(a), "l"(b), "l"(c));
    return d;
}
__device__ __forceinline__ ull dup2(float x) {
    unsigned b = __float_as_uint(x);
    return (((ull)b) << 32) | (ull)b;
}

// ---------------- K1: fp16 A-split 2-pass GMul on mma.sync ----------------
__global__ __launch_bounds__(128) void k1_gmul(const float* __restrict__ WW,
                                               const float* __restrict__ X) {
    __shared__ float4 smv[(3*ATB + BTB) / 16];
    const uint32_t sb = smem_u32(smv);
    const uint32_t Bb = sb + 3*ATB;

    const int t = threadIdx.x, warp = t >> 5, lane = t & 31;
    const int b  = blockIdx.y;
    const int n0 = blockIdx.x * MT;
    const int bz = blockIdx.z;

    const float* wwC = WW + ((size_t)(b * NPTS + n0) * NPTS + (size_t)bz * MSEG) * 3;
    const float* xC  = X + (size_t)b * NPTS * 32 + (size_t)bz * MSEG * 32;

    const int ln = t >> 1, mh = (t & 1) * 16;
    const float* wrow = wwC + (size_t)ln * (NPTS * 3) + mh * 3;
    const int mp = t >> 3, xf0 = (t & 7) * 4;
    const float* xrow = xC + 2 * mp * 32 + xf0;

    const int rw = warp * 16;
    const uint32_t aoffL = (uint32_t)(rw + (lane & 15)) * 128 + (lane >> 4) * 16;
    const uint32_t boffL = (uint32_t)(8 * (lane >> 4) + (lane & 7)) * 128 + ((lane >> 3) & 1) * 16;

    float acc[48];
#pragma unroll
    for (int i = 0; i < 48; i++) acc[i] = 0.f;

    float wf[48];
    float4 xr0, xr1;
#pragma unroll
    for (int i = 0; i < 12; i++)
        *(float4*)(wf + 4*i) = *(const float4*)(wrow + 4*i);
    xr0 = *(const float4*)(xrow);
    xr1 = *(const float4*)(xrow + 32);

    for (int c = 0; c < NCH; ++c) {
        // ---- stage A tiles (fp16 hi|lo, SW128) ----
#pragma unroll
        for (int j = 0; j < 3; j++) {
            uint32_t hw[8], lw[8];
#pragma unroll
            for (int p = 0; p < 8; p++)
                split2h(wf[(2*p) * 3 + j], wf[(2*p+1) * 3 + j], hw[p], lw[p]);
            const uint32_t tb = sb + j * ATB;
            const uint32_t rb = (uint32_t)ln * 128 + mh * 2;
            sts128(tb + SW128(rb),      hw[0], hw[1], hw[2], hw[3]);
            sts128(tb + SW128(rb + 16), hw[4], hw[5], hw[6], hw[7]);
            sts128(tb + SW128(rb + 64), lw[0], lw[1], lw[2], lw[3]);
            sts128(tb + SW128(rb + 80), lw[4], lw[5], lw[6], lw[7]);
        }
        // ---- stage B tile (x transposed, single fp16) ----
        {
            float xa[4] = { xr0.x, xr0.y, xr0.z, xr0.w };
            float xb[4] = { xr1.x, xr1.y, xr1.z, xr1.w };
#pragma unroll
            for (int ff = 0; ff < 4; ff++) {
                __half2 h2 = __float22half2_rn(make_float2(xa[ff], xb[ff]));
                uint32_t fr = (uint32_t)(xf0 + ff) * 128 + 4 * mp;
                sts32(Bb + SW128(fr), *reinterpret_cast<uint32_t*>(&h2));
            }
        }
        __syncthreads();

        if (c + 1 < NCH) {
            const float* wp = wrow + (c + 1) * (MC * 3);
#pragma unroll
            for (int i = 0; i < 12; i++)
                *(float4*)(wf + 4*i) = *(const float4*)(wp + 4*i);
            const float* xp = xrow + (c + 1) * (MC * 32);
            xr0 = *(const float4*)(xp);
            xr1 = *(const float4*)(xp + 32);
        }

        // ---- mma: 2 passes (AhB, AlB) ----
#pragma unroll
        for (int ks = 0; ks < 2; ks++) {
            uint32_t Bh[8];
            ldmx4(Bh,     Bb + SW128(boffL + ks*32));
            ldmx4(Bh + 4, Bb + SW128(boffL + 2048 + ks*32));
#pragma unroll
            for (int j = 0; j < 3; j++) {
                uint32_t Ah[4], Al[4];
                const uint32_t ab = sb + j * ATB;
                ldmx4(Ah, ab + SW128(aoffL + ks*32));
                ldmx4(Al, ab + SW128(aoffL + 64 + ks*32));
#pragma unroll
                for (int fb = 0; fb < 4; fb++) {
                    float* d = acc + j*16 + fb*4;
                    mma16816(d, Ah, Bh + 2*fb);
                    mma16816(d, Al, Bh + 2*fb);
                }
            }
        }
        __syncthreads();
    }

    const int g = lane >> 2, tq = lane & 3;
    const size_t row = (size_t)bz * ROWS + (size_t)b * NPTS + n0 + rw + g;
    float* y0 = g_yp + row * KIN;
    float* y1 = y0 + 8 * KIN;
#pragma unroll
    for (int j = 0; j < 3; j++)
#pragma unroll
        for (int fb = 0; fb < 4; fb++) {
            const float* d = acc + j*16 + fb*4;
            const int cb = j*32 + fb*8 + 2*tq;
            float2 lo = { d[0], d[1] };
            float2 hi = { d[2], d[3] };
            *(float2*)(y0 + cb) = lo;
            *(float2*)(y1 + cb) = hi;
        }
}

// ---------------- K2: partial-sum + MLP + BN partials + last-block stats ----------------
__global__ __launch_bounds__(256) void k2_mlp(const float* __restrict__ W1,
                                              const float* __restrict__ W2,
                                              const float* __restrict__ b1,
                                              const float* __restrict__ b2,
                                              const float* __restrict__ gamma,
                                              const float* __restrict__ beta,
                                              float* __restrict__ Z) {
    __shared__ __align__(16) float yT[KIN * PYT2];
    __shared__ __align__(16) float wTs[KIN * FOUT];
    __shared__ float ps[4*FOUT], pq[4*FOUT];
    __shared__ int last_s;

    const int t = threadIdx.x;
    const int row0 = blockIdx.x * K2ROWS;

#pragma unroll
    for (int i = 0; i < 3; i++) {
        int flat = i * 256 + t;
        int r = flat / 24, k4 = flat % 24;
        size_t base = ((size_t)(row0 + r)) * KIN + k4 * 4;
        float4 v0 = *(const float4*)&g_yp[base];
        float4 v1 = *(const float4*)&g_yp[base + (size_t)ROWS*KIN];
        float4 v;
        v.x = v0.x + v1.x; v.y = v0.y + v1.y;
        v.z = v0.z + v1.z; v.w = v0.w + v1.w;
        int sbi = (k4 * 4) * PYT2 + r;
        yT[sbi]            = v.x;
        yT[sbi +     PYT2] = v.y;
        yT[sbi + 2 * PYT2] = v.z;
        yT[sbi + 3 * PYT2] = v.w;
    }
#pragma unroll
    for (int i = 0; i < 3; i++) {
        int idx4 = i * 256 + t;
        int c = idx4 / 24, k4 = idx4 % 24;
        float4 a = *(const float4*)&W1[(size_t)c * KIN + k4 * 4];
        float4 d = *(const float4*)&W2[(size_t)c * KIN + k4 * 4];
        wTs[(k4*4 + 0) * FOUT + c] = a.x;
        wTs[(k4*4 + 1) * FOUT + c] = a.y;
        wTs[(k4*4 + 2) * FOUT + c] = a.z;
        wTs[(k4*4 + 3) * FOUT + c] = a.w;
        wTs[(k4*4 + 0) * FOUT + 32 + c] = d.x;
        wTs[(k4*4 + 1) * FOUT + 32 + c] = d.y;
        wTs[(k4*4 + 2) * FOUT + 32 + c] = d.z;
        wTs[(k4*4 + 3) * FOUT + 32 + c] = d.w;
    }
    __syncthreads();

    const int col = t & 63, rg = t >> 6;
    const int rbase = rg * 8;
    ull acc2[4];
#pragma unroll
    for (int q = 0; q < 4; q++) acc2[q] = 0ULL;

#pragma unroll 4
    for (int k = 0; k < KIN; k++) {
        ull wd = dup2(wTs[k * FOUT + col]);
        const float* yp = yT + k * PYT2 + rbase;
        ulonglong2 y0 = *(const ulonglong2*)(yp);
        ulonglong2 y1 = *(const ulonglong2*)(yp + 4);
        acc2[0] = fma2(y0.x, wd, acc2[0]);
        acc2[1] = fma2(y0.y, wd, acc2[1]);
        acc2[2] = fma2(y1.x, wd, acc2[2]);
        acc2[3] = fma2(y1.y, wd, acc2[3]);
    }

    const float bias = (col < 32) ? __ldg(&b1[col]) : __ldg(&b2[col - 32]);
    float s = 0.f, sq = 0.f;
#pragma unroll
    for (int q = 0; q < 4; q++) {
        union { ull u; float f[2]; } cv; cv.u = acc2[q];
#pragma unroll
        for (int h = 0; h < 2; h++) {
            float z = cv.f[h] + bias;
            if (col < 32) z = fmaxf(z, 0.f);
            Z[((size_t)row0 + rbase + 2*q + h) * FOUT + col] = z;
            s += z; sq += z * z;
        }
    }
    ps[rg * FOUT + col] = s; pq[rg * FOUT + col] = sq;
    __syncthreads();
    if (rg == 0) {
        float S = (ps[col] + ps[FOUT + col]) + (ps[2*FOUT + col] + ps[3*FOUT + col]);
        float Q = (pq[col] + pq[FOUT + col]) + (pq[2*FOUT + col] + pq[3*FOUT + col]);
        g_psum[blockIdx.x * FOUT + col] = S;
        g_psq [blockIdx.x * FOUT + col] = Q;
    }

    __threadfence();
    if (t == 0) last_s = (atomicAdd(&g_ctr, 1) == NBLK2 - 1);
    __syncthreads();
    if (last_s) {
        const int seg = t >> 6;
        float S = 0.f, Q = 0.f;
#pragma unroll 8
        for (int i = 0; i < NBLK2/4; i++) {
            int idx = (seg * (NBLK2/4) + i) * FOUT + col;
            S += g_psum[idx];
            Q += g_psq [idx];
        }
        ps[seg * FOUT + col] = S; pq[seg * FOUT + col] = Q;
        __syncthreads();
        if (t < FOUT) {
            float Sf = (ps[t] + ps[FOUT + t]) + (ps[2*FOUT + t] + ps[3*FOUT + t]);
            float Qf = (pq[t] + pq[FOUT + t]) + (pq[2*FOUT + t] + pq[3*FOUT + t]);
            float mean = Sf * (1.0f / ROWS);
            float var  = Qf * (1.0f / ROWS) - mean * mean;
            float sc   = __ldg(&gamma[t]) * rsqrtf(var + 1e-5f);
            g_coef[t]        = sc;
            g_coef[FOUT + t] = __ldg(&beta[t]) - mean * sc;
        }
        if (t == 0) g_ctr = 0;
    }
}

// ---------------- K4: in-place normalize ----------------
__global__ __launch_bounds__(256) void k4_norm(float* __restrict__ Z) {
    int i0 = blockIdx.x * 512 + threadIdx.x;
    float4* Z4 = (float4*)Z;
    float4 v0 = Z4[i0];
    float4 v1 = Z4[i0 + 256];
    int c = (i0 & 15) * 4;
    float s0 = g_coef[c],   s1 = g_coef[c+1], s2 = g_coef[c+2], s3 = g_coef[c+3];
    float h0 = g_coef[FOUT+c], h1 = g_coef[FOUT+c+1], h2 = g_coef[FOUT+c+2], h3 = g_coef[FOUT+c+3];
    v0.x = v0.x*s0 + h0; v0.y = v0.y*s1 + h1; v0.z = v0.z*s2 + h2; v0.w = v0.w*s3 + h3;
    v1.x = v1.x*s0 + h0; v1.y = v1.y*s1 + h1; v1.z = v1.z*s2 + h2; v1.w = v1.w*s3 + h3;
    Z4[i0] = v0;
    Z4[i0 + 256] = v1;
}

extern "C" void kernel_launch(void* const* d_in, const int* in_sizes, int n_in,
                              void* d_out, int out_size) {
    const float* WW    = (const float*)d_in[0];
    const float* X     = (const float*)d_in[1];
    const float* W1    = (const float*)d_in[2];
    const float* b1    = (const float*)d_in[3];
    const float* W2    = (const float*)d_in[4];
    const float* b2    = (const float*)d_in[5];
    const float* gamma = (const float*)d_in[6];
    const float* beta  = (const float*)d_in[7];
    float* Z = (float*)d_out;

    dim3 g1(NT1, BS, KSPL);
    k1_gmul<<<g1, 128>>>(WW, X);
    k2_mlp<<<NBLK2, 256>>>(W1, W2, b1, b2, gamma, beta, Z);
    k4_norm<<<(ROWS * FOUT / 4) / 512, 256>>>(Z);
}